// round 10
// baseline (speedup 1.0000x reference)
#include <cuda_runtime.h>
#include <cuda_fp16.h>
#include <cstdint>

#define BB 32
#define AA 1024
#define DD 384
#define EE 4
#define H1C 256
#define H2C 192
#define NATOMS (BB*AA)
#define TM 128
#define NT 512
#define NC1 12
#define NC2 8
#define MAXTILES 260

// ---- dynamic SMEM byte map (per CTA) ----
#define AB_OFF 0
#define AB_BUF 10240        // 128 rows x 80B fp16, double buffered
#define BBF_OFF 20480
#define BBF_BUF 20480       // 256 rows x 80B, QUAD buffered
#define H1_OFF 0            // aliases AB/BBF after layer 1: 8 chunks x 8192
#define H1_CHK 8192
#define WB_OFF 102400       // 192 rows x 80B, QUAD buffered
#define WB_BUF 15360
#define DSMEM 163840

#define W1CHUNK 20480
#define WHCHUNK 15360

// ---------------- device scratch ----------------
__device__ int   g_counts[EE];
__device__ int   g_perm[EE * NATOMS];
__device__ __align__(16) unsigned short g_W1h[EE * NC1 * 256 * 40];
__device__ __align__(16) unsigned short g_Whh[EE * NC2 * 192 * 40];

// ---------------- helpers ----------------
__device__ __forceinline__ uint32_t s2u(const void* p) {
    uint32_t a;
    asm("{ .reg .u64 t; cvta.to.shared.u64 t, %1; cvt.u32.u64 %0, t; }" : "=r"(a) : "l"(p));
    return a;
}
__device__ __forceinline__ void cp16(uint32_t dst, const void* src) {
    asm volatile("cp.async.cg.shared.global [%0], [%1], 16;" :: "r"(dst), "l"(src));
}
__device__ __forceinline__ void cp_commit() { asm volatile("cp.async.commit_group;"); }
template<int N> __device__ __forceinline__ void cp_waitg() {
    asm volatile("cp.async.wait_group %0;" :: "n"(N) : "memory");
}

__device__ __forceinline__ uint32_t pack2h(float x0, float x1) {
    __half h0 = __float2half_rn(x0);
    __half h1 = __float2half_rn(x1);
    return (uint32_t)__half_as_ushort(h0) | ((uint32_t)__half_as_ushort(h1) << 16);
}

__device__ __forceinline__ void mma_f16(float* d,
        const uint32_t* a, uint32_t b0, uint32_t b1) {
    asm volatile(
        "mma.sync.aligned.m16n8k16.row.col.f32.f16.f16.f32 "
        "{%0,%1,%2,%3}, {%4,%5,%6,%7}, {%8,%9}, {%0,%1,%2,%3};"
        : "+f"(d[0]), "+f"(d[1]), "+f"(d[2]), "+f"(d[3])
        : "r"(a[0]), "r"(a[1]), "r"(a[2]), "r"(a[3]), "r"(b0), "r"(b1));
}

__device__ __forceinline__ void ldm4(uint32_t* r, uint32_t addr) {
    asm volatile("ldmatrix.sync.aligned.m8n8.x4.shared.b16 {%0,%1,%2,%3}, [%4];"
        : "=r"(r[0]), "=r"(r[1]), "=r"(r[2]), "=r"(r[3]) : "r"(addr));
}

// ---------------- setup: bucket (blocks 0..127) + weight prep (blocks 128..199) ----------------
__global__ void bucket_prep_kernel(const int* __restrict__ species,
                                   const float* __restrict__ W1,
                                   const float* __restrict__ Wh) {
    const int tid = threadIdx.x;
    const int b = blockIdx.x;
    if (b < 128) {
        int i = b * 256 + tid;
        int lane = tid & 31;
        int e = species[i];
        unsigned mask = __match_any_sync(0xffffffffu, e);
        int leader = __ffs(mask) - 1;
        int rank = __popc(mask & ((1u << lane) - 1u));
        int base = 0;
        if (lane == leader) base = atomicAdd(&g_counts[e], __popc(mask));
        base = __shfl_sync(0xffffffffu, base, leader);
        g_perm[e * NATOMS + base + rank] = i;
        return;
    }
    const int T1 = EE * NC1 * 256;   // 12288
    const int T2 = EE * NC2 * 192;   // 6144
    int idx = (b - 128) * 256 + tid;
    if (idx < T1) {
        int e = idx / (NC1 * 256);
        int r = idx % (NC1 * 256);
        int chunk = r / 256, n = r % 256;
        const float* src = W1 + ((size_t)e * DD + chunk * 32) * H1C + n;
        uint4* dh = (uint4*)(g_W1h + (size_t)idx * 40);
        #pragma unroll
        for (int q = 0; q < 4; q++) {
            uint32_t ph[4];
            #pragma unroll
            for (int j = 0; j < 4; j++)
                ph[j] = pack2h(src[(size_t)(q * 8 + 2 * j) * H1C],
                               src[(size_t)(q * 8 + 2 * j + 1) * H1C]);
            dh[q] = make_uint4(ph[0], ph[1], ph[2], ph[3]);
        }
        dh[4] = make_uint4(0, 0, 0, 0);
    } else if (idx < T1 + T2) {
        int i2 = idx - T1;
        int e = i2 / (NC2 * 192);
        int r = i2 % (NC2 * 192);
        int chunk = r / 192, n = r % 192;
        const float* src = Wh + ((size_t)e * H1C + chunk * 32) * H2C + n;
        uint4* dh = (uint4*)(g_Whh + (size_t)i2 * 40);
        #pragma unroll
        for (int q = 0; q < 4; q++) {
            uint32_t ph[4];
            #pragma unroll
            for (int j = 0; j < 4; j++)
                ph[j] = pack2h(src[(size_t)(q * 8 + 2 * j) * H2C],
                               src[(size_t)(q * 8 + 2 * j + 1) * H2C]);
            dh[q] = make_uint4(ph[0], ph[1], ph[2], ph[3]);
        }
        dh[4] = make_uint4(0, 0, 0, 0);
    }
}

// ---------------- fused 2-layer MLP + batch reduction (fp16, 4-deep pipelines) ----------------
__global__ void __launch_bounds__(NT, 1) fused_mlp(
    const float* __restrict__ rep,
    const float* __restrict__ b1, const float* __restrict__ bh,
    const float* __restrict__ W2, const float* __restrict__ b2,
    float* __restrict__ outp)
{
    extern __shared__ __align__(16) char dsm[];
    __shared__ int   prow[TM];
    __shared__ float b1s[H1C];
    __shared__ float bhs[H2C];
    __shared__ float w2s[H2C];
    __shared__ float red[TM][4];
    __shared__ float bins[BB];

    const int tid  = threadIdx.x;
    const int w    = tid >> 5;
    const int lane = tid & 31;
    const int g    = lane >> 2;
    const int t    = lane & 3;
    const int llow = lane & 15;
    const int ahi16 = (lane >> 4) << 4;

    const int wm1 = w >> 3;        // 0..1 -> 64-row slab
    const int wn1 = w & 7;         // 0..7 -> 32-col strip
    const int wm2 = w >> 2;        // 0..3 -> 32-row slab
    const int wn2 = w & 3;         // 0..3 -> 48-col strip

    int c0 = g_counts[0], c1 = g_counts[1], c2 = g_counts[2], c3 = g_counts[3];
    int t0 = (c0 + TM - 1) / TM, t1 = (c1 + TM - 1) / TM;
    int t2 = (c2 + TM - 1) / TM, t3 = (c3 + TM - 1) / TM;
    int bid = blockIdx.x, e, tloc, cnt;
    if      (bid < t0)                { e = 0; tloc = bid;                cnt = c0; }
    else if (bid < t0 + t1)           { e = 1; tloc = bid - t0;           cnt = c1; }
    else if (bid < t0 + t1 + t2)      { e = 2; tloc = bid - t0 - t1;      cnt = c2; }
    else if (bid < t0 + t1 + t2 + t3) { e = 3; tloc = bid - t0 - t1 - t2; cnt = c3; }
    else return;

    const int row0   = tloc * TM;
    const int mcount = min(TM, cnt - row0);
    if (tid < TM)
        prow[tid] = (tid < mcount) ? g_perm[e * NATOMS + row0 + tid] : -1;
    if (tid < H1C) b1s[tid] = b1[e * H1C + tid];
    if (tid < H2C) { bhs[tid] = bh[e * H2C + tid]; w2s[tid] = W2[e * H2C + tid]; }
    if (tid < BB) bins[tid] = 0.f;
    __syncthreads();

    const uint32_t sb = s2u(dsm);
    const char* w1g = (const char*)g_W1h + (size_t)e * NC1 * W1CHUNK;
    const char* whg = (const char*)g_Whh + (size_t)e * NC2 * WHCHUNK;

    const uint32_t aoff1 = (uint32_t)((wm1 * 64 + llow) * 80 + ahi16);
    const uint32_t boff1 = (uint32_t)((wn1 * 32 + (lane & 7) + ((lane >> 4) << 3)) * 80
                                      + (((lane >> 3) & 1) << 4));
    const uint32_t boff2 = (uint32_t)((wn2 * 48 + (lane & 7) + ((lane >> 4) << 3)) * 80
                                      + (((lane >> 3) & 1) << 4));
    const uint32_t h1row2 = (uint32_t)(wm2 * 32 + llow);
    const uint32_t h1sw2  = (h1row2 & 3) << 4;
    const uint32_t h1off2 = h1row2 * 64;

    // ================== LAYER 1: D1[128x256] = A @ W1[e]^T ==================
    float acc[4][4][4];
    #pragma unroll
    for (int mt = 0; mt < 4; mt++)
        #pragma unroll
        for (int nt = 0; nt < 4; nt++)
            #pragma unroll
            for (int q = 0; q < 4; q++) acc[mt][nt][q] = 0.f;

    float4 va[2];
    // prologue: pack A(0); issue B chunks 0..2; va = A(1)
    {
        #pragma unroll
        for (int j = 0; j < 2; j++) {
            int item = tid + j * NT;
            int r = item >> 3, f = item & 7;
            int p = prow[r];
            va[j] = (p >= 0) ? __ldg((const float4*)(rep + (size_t)p * DD + f * 4))
                             : make_float4(0.f, 0.f, 0.f, 0.f);
        }
        #pragma unroll
        for (int c = 0; c < 3; c++) {
            const char* srcH = w1g + (size_t)c * W1CHUNK;
            uint32_t dst = sb + BBF_OFF + c * BBF_BUF;
            #pragma unroll 1
            for (int i = tid; i < 1280; i += NT)
                cp16(dst + i * 16, srcH + i * 16);
            cp_commit();
        }
        char* Ah = dsm + AB_OFF;
        #pragma unroll
        for (int j = 0; j < 2; j++) {
            int item = tid + j * NT;
            int r = item >> 3, f = item & 7;
            *(uint2*)(Ah + r * 80 + f * 8) =
                make_uint2(pack2h(va[j].x, va[j].y), pack2h(va[j].z, va[j].w));
        }
        #pragma unroll
        for (int j = 0; j < 2; j++) {
            int item = tid + j * NT;
            int r = item >> 3, f = item & 7;
            int p = prow[r];
            va[j] = (p >= 0) ? __ldg((const float4*)(rep + (size_t)p * DD + 32 + f * 4))
                             : make_float4(0.f, 0.f, 0.f, 0.f);
        }
    }

    for (int kc = 0; kc < NC1; kc++) {
        if (kc <= 9) cp_waitg<2>(); else if (kc == 10) cp_waitg<1>(); else cp_waitg<0>();
        __syncthreads();
        // issue chunk kc+3 (buffer (kc+3)%4 last read at chunk kc-1, safe after sync)
        if (kc + 3 < NC1) {
            const char* srcH = w1g + (size_t)(kc + 3) * W1CHUNK;
            uint32_t dst = sb + BBF_OFF + ((kc + 3) & 3) * BBF_BUF;
            #pragma unroll 1
            for (int i = tid; i < 1280; i += NT)
                cp16(dst + i * 16, srcH + i * 16);
            cp_commit();
        }
        // MMA chunk kc
        {
            const uint32_t aB = sb + AB_OFF + (kc & 1) * AB_BUF + aoff1;
            const uint32_t bB = sb + BBF_OFF + (kc & 3) * BBF_BUF + boff1;
            #pragma unroll
            for (int kk = 0; kk < 2; kk++) {
                const uint32_t kb2 = kk * 32;
                uint32_t af[4][4];
                uint32_t bf[2][4];
                ldm4(af[0], aB + kb2);
                ldm4(af[1], aB + 1280 + kb2);
                ldm4(af[2], aB + 2560 + kb2);
                ldm4(af[3], aB + 3840 + kb2);
                ldm4(bf[0], bB + kb2);
                ldm4(bf[1], bB + 1280 + kb2);
                #pragma unroll
                for (int nh = 0; nh < 2; nh++) {
                    #pragma unroll
                    for (int mt = 0; mt < 4; mt++) {
                        mma_f16(acc[mt][2 * nh],     af[mt], bf[nh][0], bf[nh][1]);
                        mma_f16(acc[mt][2 * nh + 1], af[mt], bf[nh][2], bf[nh][3]);
                    }
                }
            }
        }
        if (kc + 1 < NC1) {
            char* Ah = dsm + AB_OFF + ((kc + 1) & 1) * AB_BUF;
            #pragma unroll
            for (int j = 0; j < 2; j++) {
                int item = tid + j * NT;
                int r = item >> 3, f = item & 7;
                *(uint2*)(Ah + r * 80 + f * 8) =
                    make_uint2(pack2h(va[j].x, va[j].y), pack2h(va[j].z, va[j].w));
            }
            if (kc + 2 < NC1) {
                #pragma unroll
                for (int j = 0; j < 2; j++) {
                    int item = tid + j * NT;
                    int r = item >> 3, f = item & 7;
                    int p = prow[r];
                    va[j] = (p >= 0)
                          ? __ldg((const float4*)(rep + (size_t)p * DD + (kc + 2) * 32 + f * 4))
                          : make_float4(0.f, 0.f, 0.f, 0.f);
                }
            }
        }
    }
    __syncthreads();   // all layer-1 reads done before H1 overwrites A/B buffers

    // ---- issue Wh chunks 0..2 (WB region disjoint from H1) ----
    #pragma unroll
    for (int c = 0; c < 3; c++) {
        const char* srcH = whg + (size_t)c * WHCHUNK;
        uint32_t dst = sb + WB_OFF + c * WB_BUF;
        #pragma unroll 1
        for (int i = tid; i < 960; i += NT)
            cp16(dst + i * 16, srcH + i * 16);
        cp_commit();
    }

    // ---- H1 = D1 + b1 (NO relu — reference quirk) -> chunked swizzled smem ----
    {
        char* Hh = dsm + H1_OFF;
        #pragma unroll
        for (int mt = 0; mt < 4; mt++) {
            #pragma unroll
            for (int nt = 0; nt < 4; nt++) {
                int kin = nt * 8 + 2 * t;
                int c0i = wn1 * 32 + kin;
                int r0 = wm1 * 64 + mt * 16 + g, r1 = r0 + 8;
                uint32_t o0 = wn1 * H1_CHK + r0 * 64 + ((kin * 2) ^ ((r0 & 3) << 4));
                *(uint32_t*)(Hh + o0) =
                    pack2h(acc[mt][nt][0] + b1s[c0i], acc[mt][nt][1] + b1s[c0i + 1]);
                uint32_t o1 = wn1 * H1_CHK + r1 * 64 + ((kin * 2) ^ ((r1 & 3) << 4));
                *(uint32_t*)(Hh + o1) =
                    pack2h(acc[mt][nt][2] + b1s[c0i], acc[mt][nt][3] + b1s[c0i + 1]);
            }
        }
    }

    // ================== LAYER 2: D2[128x192] = H1 @ Wh[e]^T ==================
    float acc2[2][6][4];
    #pragma unroll
    for (int mt = 0; mt < 2; mt++)
        #pragma unroll
        for (int nt = 0; nt < 6; nt++)
            #pragma unroll
            for (int q = 0; q < 4; q++) acc2[mt][nt][q] = 0.f;

    for (int kc = 0; kc < NC2; kc++) {
        if (kc <= 5) cp_waitg<2>(); else if (kc == 6) cp_waitg<1>(); else cp_waitg<0>();
        __syncthreads();
        if (kc + 3 < NC2) {
            const char* srcH = whg + (size_t)(kc + 3) * WHCHUNK;
            uint32_t dst = sb + WB_OFF + ((kc + 3) & 3) * WB_BUF;
            #pragma unroll 1
            for (int i = tid; i < 960; i += NT)
                cp16(dst + i * 16, srcH + i * 16);
            cp_commit();
        }
        {
            const uint32_t bB = sb + WB_OFF + (kc & 3) * WB_BUF + boff2;
            const uint32_t aH = sb + H1_OFF + kc * H1_CHK;
            #pragma unroll
            for (int kk = 0; kk < 2; kk++) {
                const uint32_t kb2 = kk * 32;
                const uint32_t colsw = (kb2 + ahi16) ^ h1sw2;
                uint32_t ah0[4], ah1[4];
                uint32_t bf[3][4];
                ldm4(ah0, aH + h1off2 + colsw);
                ldm4(ah1, aH + h1off2 + 1024 + colsw);
                ldm4(bf[0], bB + kb2);
                ldm4(bf[1], bB + 1280 + kb2);
                ldm4(bf[2], bB + 2560 + kb2);
                #pragma unroll
                for (int pg = 0; pg < 3; pg++) {
                    mma_f16(acc2[0][2 * pg],     ah0, bf[pg][0], bf[pg][1]);
                    mma_f16(acc2[1][2 * pg],     ah1, bf[pg][0], bf[pg][1]);
                    mma_f16(acc2[0][2 * pg + 1], ah0, bf[pg][2], bf[pg][3]);
                    mma_f16(acc2[1][2 * pg + 1], ah1, bf[pg][2], bf[pg][3]);
                }
            }
        }
    }

    // ---- fused epilogue: E = relu(D2 + bh) . W2 + b2, per-batch bins ----
    {
        const int C0 = wn2 * 48;
        const int R0 = wm2 * 32;
        float pv[2][2] = {{0.f, 0.f}, {0.f, 0.f}};
        #pragma unroll
        for (int mt = 0; mt < 2; mt++) {
            #pragma unroll
            for (int nt = 0; nt < 6; nt++) {
                int c0i = C0 + nt * 8 + 2 * t;
                float bb0 = bhs[c0i],     w0 = w2s[c0i];
                float bb1 = bhs[c0i + 1], w1v = w2s[c0i + 1];
                float v;
                v = acc2[mt][nt][0] + bb0; v = v > 0.f ? v : 0.f; pv[mt][0] = fmaf(v, w0,  pv[mt][0]);
                v = acc2[mt][nt][1] + bb1; v = v > 0.f ? v : 0.f; pv[mt][0] = fmaf(v, w1v, pv[mt][0]);
                v = acc2[mt][nt][2] + bb0; v = v > 0.f ? v : 0.f; pv[mt][1] = fmaf(v, w0,  pv[mt][1]);
                v = acc2[mt][nt][3] + bb1; v = v > 0.f ? v : 0.f; pv[mt][1] = fmaf(v, w1v, pv[mt][1]);
            }
        }
        #pragma unroll
        for (int mt = 0; mt < 2; mt++) {
            #pragma unroll
            for (int h = 0; h < 2; h++) {
                pv[mt][h] += __shfl_xor_sync(0xffffffffu, pv[mt][h], 1);
                pv[mt][h] += __shfl_xor_sync(0xffffffffu, pv[mt][h], 2);
            }
        }
        __syncthreads();
        if (t == 0) {
            #pragma unroll
            for (int mt = 0; mt < 2; mt++) {
                red[R0 + mt * 16 + g][wn2]     = pv[mt][0];
                red[R0 + mt * 16 + 8 + g][wn2] = pv[mt][1];
            }
        }
        __syncthreads();
        if (tid < TM) {
            int pr = prow[tid];
            if (pr >= 0) {
                float en = red[tid][0] + red[tid][1] + red[tid][2] + red[tid][3] + b2[e];
                atomicAdd(&bins[pr >> 10], en);
            }
        }
        __syncthreads();
        if (tid < BB) {
            float v = bins[tid];
            if (v != 0.f) atomicAdd(&outp[tid], v);
        }
    }
}

extern "C" void kernel_launch(void* const* d_in, const int* in_sizes, int n_in,
                              void* d_out, int out_size) {
    const float* rep     = (const float*)d_in[0];
    const int*   species = (const int*)  d_in[1];
    const float* W1      = (const float*)d_in[2];
    const float* b1      = (const float*)d_in[3];
    const float* Wh      = (const float*)d_in[4];
    const float* bh      = (const float*)d_in[5];
    const float* W2      = (const float*)d_in[6];
    const float* b2      = (const float*)d_in[7];
    float* out = (float*)d_out;

    cudaFuncSetAttribute(fused_mlp,
                         cudaFuncAttributeMaxDynamicSharedMemorySize, DSMEM);

    void* cptr = nullptr;
    cudaGetSymbolAddress(&cptr, g_counts);
    cudaMemsetAsync(cptr, 0, EE * sizeof(int), 0);
    cudaMemsetAsync(out, 0, BB * sizeof(float), 0);
    bucket_prep_kernel<<<200, 256>>>(species, W1, Wh);
    fused_mlp<<<MAXTILES, NT, DSMEM>>>(rep, b1, bh, W2, b2, out);
}

// round 11
// speedup vs baseline: 1.1119x; 1.1119x over previous
#include <cuda_runtime.h>
#include <cuda_fp16.h>
#include <cstdint>

#define BB 32
#define AA 1024
#define DD 384
#define EE 4
#define H1C 256
#define H2C 192
#define NATOMS (BB*AA)
#define TM 128
#define NT 512
#define MAXTILES 260

// ---- dynamic SMEM byte map (per CTA) ----
// A: 12 chunks (k32) x 128 rows x 80B = 122880
// H1: 8 chunks (k32) x 128 rows x 64B = 65536
#define A_CHK 10240
#define A_SZ  122880
#define H1_OFF 122880
#define H1_CHK 8192
#define DSMEM 188416

// fragment-ordered weights: [e][kc2][n8][lane] as uint2 {b0,b1}
#define W1F_N (EE * 24 * 32 * 32)   // 98304
#define WHF_N (EE * 16 * 24 * 32)   // 49152

// ---------------- device scratch ----------------
__device__ int   g_counts[EE];
__device__ int   g_perm[EE * NATOMS];
__device__ __align__(16) uint2 g_W1f[W1F_N];
__device__ __align__(16) uint2 g_Whf[WHF_N];

// ---------------- helpers ----------------
__device__ __forceinline__ uint32_t s2u(const void* p) {
    uint32_t a;
    asm("{ .reg .u64 t; cvta.to.shared.u64 t, %1; cvt.u32.u64 %0, t; }" : "=r"(a) : "l"(p));
    return a;
}

__device__ __forceinline__ uint32_t pack2h(float x0, float x1) {
    __half2 h = __floats2half2_rn(x0, x1);   // x0 -> low half
    return *(uint32_t*)&h;
}

__device__ __forceinline__ void mma_f16(float* d,
        const uint32_t* a, uint32_t b0, uint32_t b1) {
    asm volatile(
        "mma.sync.aligned.m16n8k16.row.col.f32.f16.f16.f32 "
        "{%0,%1,%2,%3}, {%4,%5,%6,%7}, {%8,%9}, {%0,%1,%2,%3};"
        : "+f"(d[0]), "+f"(d[1]), "+f"(d[2]), "+f"(d[3])
        : "r"(a[0]), "r"(a[1]), "r"(a[2]), "r"(a[3]), "r"(b0), "r"(b1));
}

__device__ __forceinline__ void ldm4(uint32_t* r, uint32_t addr) {
    asm volatile("ldmatrix.sync.aligned.m8n8.x4.shared.b16 {%0,%1,%2,%3}, [%4];"
        : "=r"(r[0]), "=r"(r[1]), "=r"(r[2]), "=r"(r[3]) : "r"(addr));
}

// ---------------- setup: bucket (blocks 0..127) + fragment prep (blocks 128..703) ----------------
__global__ void bucket_prep_kernel(const int* __restrict__ species,
                                   const float* __restrict__ W1,
                                   const float* __restrict__ Wh) {
    const int tid = threadIdx.x;
    const int b = blockIdx.x;
    if (b < 128) {
        int i = b * 256 + tid;
        int lane = tid & 31;
        int e = species[i];
        unsigned mask = __match_any_sync(0xffffffffu, e);
        int leader = __ffs(mask) - 1;
        int rank = __popc(mask & ((1u << lane) - 1u));
        int base = 0;
        if (lane == leader) base = atomicAdd(&g_counts[e], __popc(mask));
        base = __shfl_sync(0xffffffffu, base, leader);
        g_perm[e * NATOMS + base + rank] = i;
        return;
    }
    int idx = (b - 128) * 256 + tid;
    if (idx < W1F_N) {
        int lane = idx & 31;
        int n8   = (idx >> 5) & 31;
        int rest = idx >> 10;
        int kc2  = rest % 24;
        int e    = rest / 24;
        int k = kc2 * 16 + 2 * (lane & 3);
        int n = n8 * 8 + (lane >> 2);
        const float* Wp = W1 + ((size_t)e * DD + k) * H1C + n;
        uint32_t b0 = pack2h(Wp[0],              Wp[H1C]);
        uint32_t b1 = pack2h(Wp[(size_t)8 * H1C], Wp[(size_t)9 * H1C]);
        g_W1f[idx] = make_uint2(b0, b1);
    } else if (idx < W1F_N + WHF_N) {
        int i2 = idx - W1F_N;
        int lane = i2 & 31;
        int tmp  = i2 >> 5;
        int n8   = tmp % 24;
        int rest = tmp / 24;
        int kc2  = rest % 16;
        int e    = rest / 16;
        int k = kc2 * 16 + 2 * (lane & 3);
        int n = n8 * 8 + (lane >> 2);
        const float* Wp = Wh + ((size_t)e * H1C + k) * H2C + n;
        uint32_t b0 = pack2h(Wp[0],              Wp[H2C]);
        uint32_t b1 = pack2h(Wp[(size_t)8 * H2C], Wp[(size_t)9 * H2C]);
        g_Whf[i2] = make_uint2(b0, b1);
    }
}

// ---------------- fused 2-layer MLP + batch reduction (sync-free mainloops) ----------------
__global__ void __launch_bounds__(NT, 1) fused_mlp(
    const float* __restrict__ rep,
    const float* __restrict__ b1, const float* __restrict__ bh,
    const float* __restrict__ W2, const float* __restrict__ b2,
    float* __restrict__ outp)
{
    extern __shared__ __align__(16) char dsm[];
    __shared__ int   prow[TM];
    __shared__ float b1s[H1C];
    __shared__ float bhs[H2C];
    __shared__ float w2s[H2C];
    __shared__ float red[TM][4];
    __shared__ float bins[BB];

    const int tid  = threadIdx.x;
    const int w    = tid >> 5;
    const int lane = tid & 31;
    const int g    = lane >> 2;
    const int t    = lane & 3;
    const int llow = lane & 15;
    const int ahi16 = (lane >> 4) << 4;

    const int wm1 = w >> 3;        // 0..1 -> 64-row slab
    const int wn1 = w & 7;         // 0..7 -> 32-col strip
    const int wm2 = w >> 2;        // 0..3 -> 32-row slab
    const int wn2 = w & 3;         // 0..3 -> 48-col strip

    int c0 = g_counts[0], c1 = g_counts[1], c2 = g_counts[2], c3 = g_counts[3];
    int t0 = (c0 + TM - 1) / TM, t1 = (c1 + TM - 1) / TM;
    int t2 = (c2 + TM - 1) / TM, t3 = (c3 + TM - 1) / TM;
    int bid = blockIdx.x, e, tloc, cnt;
    if      (bid < t0)                { e = 0; tloc = bid;                cnt = c0; }
    else if (bid < t0 + t1)           { e = 1; tloc = bid - t0;           cnt = c1; }
    else if (bid < t0 + t1 + t2)      { e = 2; tloc = bid - t0 - t1;      cnt = c2; }
    else if (bid < t0 + t1 + t2 + t3) { e = 3; tloc = bid - t0 - t1 - t2; cnt = c3; }
    else return;

    const int row0   = tloc * TM;
    const int mcount = min(TM, cnt - row0);
    if (tid < TM)
        prow[tid] = (tid < mcount) ? g_perm[e * NATOMS + row0 + tid] : -1;
    if (tid < H1C) b1s[tid] = b1[e * H1C + tid];
    if (tid < H2C) { bhs[tid] = bh[e * H2C + tid]; w2s[tid] = W2[e * H2C + tid]; }
    if (tid < BB) bins[tid] = 0.f;
    __syncthreads();

    const uint32_t sb = s2u(dsm);

    // ---- pack FULL A tile (128 x 384) fp16 into chunked smem, once ----
    {
        int r = tid >> 2;             // 128 rows, 4 threads per row
        int fq = tid & 3;             // each thread: 2 float4 groups per chunk
        int p = prow[r];
        const float4* src = (p >= 0) ? (const float4*)(rep + (size_t)p * DD) : nullptr;
        char* Arow = dsm + r * 80;
        #pragma unroll 3
        for (int c = 0; c < 12; c++) {
            #pragma unroll
            for (int j = 0; j < 2; j++) {
                int f = fq * 2 + j;   // 0..7 within chunk
                float4 v = src ? __ldg(src + c * 8 + f) : make_float4(0.f, 0.f, 0.f, 0.f);
                *(uint2*)(Arow + c * A_CHK + f * 8) =
                    make_uint2(pack2h(v.x, v.y), pack2h(v.z, v.w));
            }
        }
    }
    __syncthreads();

    // ================== LAYER 1: D1[128x256] = A @ W1[e]^T (sync-free) ==================
    const uint32_t aB1 = sb + (uint32_t)((wm1 * 64 + llow) * 80 + ahi16);
    const uint2* __restrict__ w1f = g_W1f + ((size_t)(e * 24) * 32 + wn1 * 4) * 32 + lane;

    float acc[4][4][4];
    #pragma unroll
    for (int mt = 0; mt < 4; mt++)
        #pragma unroll
        for (int nt = 0; nt < 4; nt++)
            #pragma unroll
            for (int q = 0; q < 4; q++) acc[mt][nt][q] = 0.f;

    #pragma unroll 2
    for (int kc2 = 0; kc2 < 24; kc2++) {
        const uint32_t aB = aB1 + (kc2 >> 1) * A_CHK + (kc2 & 1) * 32;
        uint2 bf0 = __ldg(w1f + kc2 * 1024);
        uint2 bf1 = __ldg(w1f + kc2 * 1024 + 32);
        uint2 bf2 = __ldg(w1f + kc2 * 1024 + 64);
        uint2 bf3 = __ldg(w1f + kc2 * 1024 + 96);
        uint32_t af[4][4];
        ldm4(af[0], aB);
        ldm4(af[1], aB + 1280);
        ldm4(af[2], aB + 2560);
        ldm4(af[3], aB + 3840);
        #pragma unroll
        for (int mt = 0; mt < 4; mt++) {
            mma_f16(acc[mt][0], af[mt], bf0.x, bf0.y);
            mma_f16(acc[mt][1], af[mt], bf1.x, bf1.y);
            mma_f16(acc[mt][2], af[mt], bf2.x, bf2.y);
            mma_f16(acc[mt][3], af[mt], bf3.x, bf3.y);
        }
    }

    // ---- H1 = D1 + b1 (NO relu — reference quirk) -> chunked swizzled smem ----
    {
        char* Hh = dsm + H1_OFF;
        #pragma unroll
        for (int mt = 0; mt < 4; mt++) {
            #pragma unroll
            for (int nt = 0; nt < 4; nt++) {
                int kin = nt * 8 + 2 * t;
                int c0i = wn1 * 32 + kin;
                int r0 = wm1 * 64 + mt * 16 + g, r1 = r0 + 8;
                uint32_t o0 = wn1 * H1_CHK + r0 * 64 + ((kin * 2) ^ ((r0 & 3) << 4));
                *(uint32_t*)(Hh + o0) =
                    pack2h(acc[mt][nt][0] + b1s[c0i], acc[mt][nt][1] + b1s[c0i + 1]);
                uint32_t o1 = wn1 * H1_CHK + r1 * 64 + ((kin * 2) ^ ((r1 & 3) << 4));
                *(uint32_t*)(Hh + o1) =
                    pack2h(acc[mt][nt][2] + b1s[c0i], acc[mt][nt][3] + b1s[c0i + 1]);
            }
        }
    }
    __syncthreads();

    // ================== LAYER 2: D2[128x192] = H1 @ Wh[e]^T (sync-free) ==================
    const uint32_t h1row2 = (uint32_t)(wm2 * 32 + llow);
    const uint32_t h1sw2  = (h1row2 & 3) << 4;
    const uint32_t aH2    = sb + H1_OFF + h1row2 * 64;
    const uint2* __restrict__ whf = g_Whf + ((size_t)(e * 16) * 24 + wn2 * 6) * 32 + lane;

    float acc2[2][6][4];
    #pragma unroll
    for (int mt = 0; mt < 2; mt++)
        #pragma unroll
        for (int nt = 0; nt < 6; nt++)
            #pragma unroll
            for (int q = 0; q < 4; q++) acc2[mt][nt][q] = 0.f;

    #pragma unroll 2
    for (int kc2 = 0; kc2 < 16; kc2++) {
        const uint32_t colsw = (((kc2 & 1) << 5) + ahi16) ^ h1sw2;
        const uint32_t aH = aH2 + (kc2 >> 1) * H1_CHK + colsw;
        uint2 bf[6];
        #pragma unroll
        for (int j = 0; j < 6; j++)
            bf[j] = __ldg(whf + kc2 * 768 + j * 32);
        uint32_t ah0[4], ah1[4];
        ldm4(ah0, aH);
        ldm4(ah1, aH + 1024);
        #pragma unroll
        for (int j = 0; j < 6; j++) {
            mma_f16(acc2[0][j], ah0, bf[j].x, bf[j].y);
            mma_f16(acc2[1][j], ah1, bf[j].x, bf[j].y);
        }
    }

    // ---- fused epilogue: E = relu(D2 + bh) . W2 + b2, per-batch bins ----
    {
        const int C0 = wn2 * 48;
        const int R0 = wm2 * 32;
        float pv[2][2] = {{0.f, 0.f}, {0.f, 0.f}};
        #pragma unroll
        for (int mt = 0; mt < 2; mt++) {
            #pragma unroll
            for (int nt = 0; nt < 6; nt++) {
                int c0i = C0 + nt * 8 + 2 * t;
                float bb0 = bhs[c0i],     w0 = w2s[c0i];
                float bb1 = bhs[c0i + 1], w1v = w2s[c0i + 1];
                float v;
                v = acc2[mt][nt][0] + bb0; v = v > 0.f ? v : 0.f; pv[mt][0] = fmaf(v, w0,  pv[mt][0]);
                v = acc2[mt][nt][1] + bb1; v = v > 0.f ? v : 0.f; pv[mt][0] = fmaf(v, w1v, pv[mt][0]);
                v = acc2[mt][nt][2] + bb0; v = v > 0.f ? v : 0.f; pv[mt][1] = fmaf(v, w0,  pv[mt][1]);
                v = acc2[mt][nt][3] + bb1; v = v > 0.f ? v : 0.f; pv[mt][1] = fmaf(v, w1v, pv[mt][1]);
            }
        }
        #pragma unroll
        for (int mt = 0; mt < 2; mt++) {
            #pragma unroll
            for (int h = 0; h < 2; h++) {
                pv[mt][h] += __shfl_xor_sync(0xffffffffu, pv[mt][h], 1);
                pv[mt][h] += __shfl_xor_sync(0xffffffffu, pv[mt][h], 2);
            }
        }
        if (t == 0) {
            #pragma unroll
            for (int mt = 0; mt < 2; mt++) {
                red[R0 + mt * 16 + g][wn2]     = pv[mt][0];
                red[R0 + mt * 16 + 8 + g][wn2] = pv[mt][1];
            }
        }
        __syncthreads();
        if (tid < TM) {
            int pr = prow[tid];
            if (pr >= 0) {
                float en = red[tid][0] + red[tid][1] + red[tid][2] + red[tid][3] + b2[e];
                atomicAdd(&bins[pr >> 10], en);
            }
        }
        __syncthreads();
        if (tid < BB) {
            float v = bins[tid];
            if (v != 0.f) atomicAdd(&outp[tid], v);
        }
    }
}

extern "C" void kernel_launch(void* const* d_in, const int* in_sizes, int n_in,
                              void* d_out, int out_size) {
    const float* rep     = (const float*)d_in[0];
    const int*   species = (const int*)  d_in[1];
    const float* W1      = (const float*)d_in[2];
    const float* b1      = (const float*)d_in[3];
    const float* Wh      = (const float*)d_in[4];
    const float* bh      = (const float*)d_in[5];
    const float* W2      = (const float*)d_in[6];
    const float* b2      = (const float*)d_in[7];
    float* out = (float*)d_out;

    cudaFuncSetAttribute(fused_mlp,
                         cudaFuncAttributeMaxDynamicSharedMemorySize, DSMEM);

    void* cptr = nullptr;
    cudaGetSymbolAddress(&cptr, g_counts);
    cudaMemsetAsync(cptr, 0, EE * sizeof(int), 0);
    cudaMemsetAsync(out, 0, BB * sizeof(float), 0);
    const int FRAG = W1F_N + WHF_N;                 // 147456
    bucket_prep_kernel<<<128 + (FRAG + 255) / 256, 256>>>(species, W1, Wh);
    fused_mlp<<<MAXTILES, NT, DSMEM>>>(rep, b1, bh, W2, b2, out);
}